// round 4
// baseline (speedup 1.0000x reference)
#include <cuda_runtime.h>

#define B_   1024
#define C_   128
#define L_   16
#define EQ_  3
#define E_   10
#define P3_  23
#define P2_  5
#define NP_  136    // symmetric pairs  (a<=b)
#define NM_  816    // symmetric triples (a<=b<=d)
#define NF_  992    // padded feature length: 816 z + 136 zp + 16 x + 24 pad
#define NCH_ 31     // NF_/32

// Scratch (__device__ globals — no allocation)
__device__ float g_U3sym[EQ_ * NM_ * P3_];          // 225 KB
__device__ float g_U2sym[EQ_ * NP_ * P2_];          // 8 KB
__device__ float g_coeff[(size_t)E_ * C_ * EQ_ * NF_]; // 15.2 MB
__device__ unsigned g_tab_m[NM_];                   // (d<<16)|p
__device__ unsigned g_tab_pr[NP_];                  // (a<<16)|b
__device__ int g_cnt[E_];
__device__ int g_nodes[E_ * B_];

__host__ __device__ __forceinline__ int Tet(int d) { return d * (d + 1) * (d + 2) / 6; }

// ---------------- setup: index tables + counters -------------------------
__global__ void k_setup() {
    int t = threadIdx.x;
    if (t < E_) g_cnt[t] = 0;
    for (int p = t; p < NP_; p += 256) {
        int b = 0;
        while ((b + 1) * (b + 2) / 2 <= p) b++;
        int a = p - b * (b + 1) / 2;
        g_tab_pr[p] = ((unsigned)a << 16) | (unsigned)b;
    }
    for (int m = t; m < NM_; m += 256) {
        int d = 0;
        while (Tet(d + 1) <= m) d++;
        int p = m - Tet(d);
        g_tab_m[m] = ((unsigned)d << 16) | (unsigned)p;
    }
}

__global__ void k_classify(const float* __restrict__ y) {
    int b = blockIdx.x * blockDim.x + threadIdx.x;
    if (b >= B_) return;
    int e = 0;
    #pragma unroll
    for (int j = 0; j < E_; j++)
        if (y[b * E_ + j] > 0.5f) e = j;
    int idx = atomicAdd(&g_cnt[e], 1);
    g_nodes[e * B_ + idx] = b;
}

// ---------------- symmetrize U3 (per w,k) and U2 -------------------------
// grid: 84 = 69 (3w x 23k for U3) + 15 (3w x 5k for U2)
__global__ __launch_bounds__(256) void k_sym(
    const float* __restrict__ U3, const float* __restrict__ U2) {
    __shared__ float s[NM_];
    int t = threadIdx.x;
    int bid = blockIdx.x;
    if (bid < 69) {
        int w = bid / P3_, k = bid % P3_;
        for (int i = t; i < NM_; i += 256) s[i] = 0.f;
        __syncthreads();
        for (int idx = t; idx < 4096; idx += 256) {
            int xx = idx >> 8, v = (idx >> 4) & 15, i = idx & 15;
            float val = U3[((((w * L_ + xx) * L_ + v) * L_ + i) * P3_) + k];
            int hi = max(xx, max(v, i));
            int lo = min(xx, min(v, i));
            int mid = xx + v + i - hi - lo;
            int m = Tet(hi) + mid * (mid + 1) / 2 + lo;
            atomicAdd(&s[m], val);
        }
        __syncthreads();
        for (int m = t; m < NM_; m += 256)
            g_U3sym[(w * NM_ + m) * P3_ + k] = s[m];
    } else {
        int b2 = bid - 69;
        int w = b2 / P2_, k = b2 % P2_;
        for (int i = t; i < NP_; i += 256) s[i] = 0.f;
        __syncthreads();
        for (int idx = t; idx < 256; idx += 256) {
            int xx = idx >> 4, v = idx & 15;
            float val = U2[((w * L_ + xx) * L_ + v) * P2_ + k];
            int hi = max(xx, v), lo = min(xx, v);
            int p = hi * (hi + 1) / 2 + lo;
            atomicAdd(&s[p], val);
        }
        __syncthreads();
        for (int p = t; p < NP_; p += 256)
            g_U2sym[(w * NP_ + p) * P2_ + k] = s[p];
    }
}

// ---------------- coeff GEMM, triple part: (3*816,23)@(23, 1280ec) --------
// grid 10 x 256: col = w*816+m < 2448
__global__ __launch_bounds__(256) void k_coeffA(const float* __restrict__ wmax) {
    __shared__ float ws[P3_][C_];
    int t = threadIdx.x;
    int col = blockIdx.x * 256 + t;
    bool act = col < EQ_ * NM_;
    int w = 0, m = 0;
    float u[P3_];
    if (act) {
        w = col / NM_; m = col % NM_;
        #pragma unroll
        for (int k = 0; k < P3_; k++) u[k] = g_U3sym[(w * NM_ + m) * P3_ + k];
    }
    for (int e = 0; e < E_; e++) {
        __syncthreads();
        for (int idx = t; idx < P3_ * C_; idx += 256) {
            int row = idx >> 7, c = idx & 127;
            ws[row][c] = wmax[(e * P3_ + row) * C_ + c];
        }
        __syncthreads();
        if (act) {
            for (int c = 0; c < C_; c++) {
                float sacc = 0.f;
                #pragma unroll
                for (int k = 0; k < P3_; k++) sacc += u[k] * ws[k][c];
                g_coeff[((size_t)(e * C_ + c) * EQ_ + w) * NF_ + m] = sacc;
            }
        }
    }
}

// ---------------- coeff, pair + linear + pad part: j in [816,992) ---------
// grid 3 (w), block 192 (t<176)
__global__ void k_coeffB(const float* __restrict__ U1,
                         const float* __restrict__ w2,
                         const float* __restrict__ w1) {
    int t = threadIdx.x;
    if (t >= 176) return;
    int w = blockIdx.x;
    float u[P2_] = {0, 0, 0, 0, 0};
    if (t < NP_) {
        #pragma unroll
        for (int k = 0; k < P2_; k++) u[k] = g_U2sym[(w * NP_ + t) * P2_ + k];
    }
    float u1v = (t >= NP_ && t < NP_ + L_) ? U1[w * L_ + (t - NP_)] : 0.f;
    for (int ec = 0; ec < E_ * C_; ec++) {
        int e = ec >> 7, c = ec & 127;
        float s = 0.f;
        if (t < NP_) {
            #pragma unroll
            for (int k = 0; k < P2_; k++) s += u[k] * __ldg(&w2[(e * P2_ + k) * C_ + c]);
        } else if (t < NP_ + L_) {
            s = u1v * __ldg(&w1[e * C_ + c]);
        }
        g_coeff[((size_t)ec * EQ_ + w) * NF_ + NM_ + t] = s;
    }
}

// ---------------- main: block per (c,e); warp per node --------------------
__global__ __launch_bounds__(256, 2) void k_main(
    const float* __restrict__ x, float* __restrict__ out) {
    __shared__ float F[8][NF_];
    __shared__ unsigned s_tm[NM_];
    __shared__ unsigned s_tp[NP_];

    int t = threadIdx.x;
    int warp = t >> 5, lane = t & 31;
    int c = blockIdx.x, e = blockIdx.y;

    // per-lane coefficient registers: cf[w][r] for feature j = lane + 32r
    const float* cfb = g_coeff + (size_t)(e * C_ + c) * EQ_ * NF_;
    float cf0[NCH_], cf1[NCH_], cf2[NCH_];
    #pragma unroll
    for (int r = 0; r < NCH_; r++) {
        cf0[r] = cfb[0 * NF_ + lane + 32 * r];
        cf1[r] = cfb[1 * NF_ + lane + 32 * r];
        cf2[r] = cfb[2 * NF_ + lane + 32 * r];
    }
    for (int i = t; i < NM_; i += 256) s_tm[i] = g_tab_m[i];
    for (int i = t; i < NP_; i += 256) s_tp[i] = g_tab_pr[i];
    if (lane < 24) F[warp][NM_ + NP_ + L_ + lane] = 0.f;  // pad region
    __syncthreads();

    int nb = g_cnt[e];
    float* Fw = F[warp];
    float* xw = Fw + NM_ + NP_;

    for (int jn = warp; jn < nb; jn += 8) {
        int b = g_nodes[e * B_ + jn];
        if (lane < L_) xw[lane] = x[((size_t)b * C_ + c) * L_ + lane];
        __syncwarp();
        // pairs: zp[p] = x_a * x_b
        #pragma unroll
        for (int r = 0; r < 5; r++) {
            int p = lane + 32 * r;
            if (p < NP_) {
                unsigned ab = s_tp[p];
                Fw[NM_ + p] = xw[ab >> 16] * xw[ab & 0xffff];
            }
        }
        __syncwarp();
        // triples: z[m] = zp[p] * x_d
        #pragma unroll
        for (int r = 0; r < 26; r++) {
            int m = lane + 32 * r;
            if (m < NM_) {
                unsigned dp = s_tm[m];
                Fw[m] = Fw[NM_ + (dp & 0xffff)] * xw[dp >> 16];
            }
        }
        __syncwarp();
        // dot: out[w] = sum_j coeff[w][j] * F[j]
        float a0 = 0.f, a1 = 0.f, a2 = 0.f;
        #pragma unroll
        for (int r = 0; r < NCH_; r++) {
            float f = Fw[lane + 32 * r];
            a0 += f * cf0[r];
            a1 += f * cf1[r];
            a2 += f * cf2[r];
        }
        #pragma unroll
        for (int msk = 16; msk >= 1; msk >>= 1) {
            a0 += __shfl_xor_sync(0xffffffffu, a0, msk);
            a1 += __shfl_xor_sync(0xffffffffu, a1, msk);
            a2 += __shfl_xor_sync(0xffffffffu, a2, msk);
        }
        if (lane == 0) {
            float* o = out + ((size_t)b * C_ + c) * EQ_;
            o[0] = a0; o[1] = a1; o[2] = a2;
        }
        __syncwarp();
    }
}

extern "C" void kernel_launch(void* const* d_in, const int* in_sizes, int n_in,
                              void* d_out, int out_size) {
    const float* x    = (const float*)d_in[0];
    const float* y    = (const float*)d_in[1];
    const float* U3   = (const float*)d_in[2];
    const float* U2   = (const float*)d_in[3];
    const float* U1   = (const float*)d_in[4];
    const float* wmax = (const float*)d_in[5];
    const float* w2   = (const float*)d_in[6];
    const float* w1   = (const float*)d_in[7];
    float* out = (float*)d_out;

    k_setup<<<1, 256>>>();
    k_classify<<<4, 256>>>(y);
    k_sym<<<84, 256>>>(U3, U2);
    k_coeffA<<<10, 256>>>(wmax);
    k_coeffB<<<3, 192>>>(U1, w2, w1);
    k_main<<<dim3(C_, E_), 256>>>(x, out);
}

// round 5
// speedup vs baseline: 3.7793x; 3.7793x over previous
#include <cuda_runtime.h>

#define B_   1024
#define C_   128
#define L_   16
#define EQ_  3
#define E_   10
#define P3_  23
#define P2_  5
#define NP_  136    // symmetric pairs  (a<=b)
#define NM_  816    // symmetric triples (lo<=mid<=hi)
#define NF2_ 1024   // padded feature len: [0,816) triples, [816,952) pairs, [952,968) x, [968,1024) pad
#define NCH2_ 16    // NF2_/64

// Scratch (__device__ globals — no allocation)
__device__ float g_U3sym[EQ_ * NM_ * P3_];             // 225 KB
__device__ float g_U2sym[EQ_ * NP_ * P2_];             // 8 KB
__device__ float g_coeff[(size_t)E_ * C_ * EQ_ * NF2_]; // 15.7 MB
__device__ unsigned g_tab_m[NM_];                      // (d<<16)|p
__device__ unsigned g_tab_pr[NP_];                     // (a<<16)|b
__device__ int g_cnt[E_];
__device__ int g_nodes[E_ * B_];

__host__ __device__ __forceinline__ int Tet(int d) { return d * (d + 1) * (d + 2) / 6; }

// ---------------- setup: index tables + counters -------------------------
__global__ void k_setup() {
    int t = threadIdx.x;
    if (t < E_) g_cnt[t] = 0;
    for (int p = t; p < NP_; p += 256) {
        int b = 0;
        while ((b + 1) * (b + 2) / 2 <= p) b++;
        int a = p - b * (b + 1) / 2;
        g_tab_pr[p] = ((unsigned)a << 16) | (unsigned)b;
    }
    for (int m = t; m < NM_; m += 256) {
        int d = 0;
        while (Tet(d + 1) <= m) d++;
        int p = m - Tet(d);
        g_tab_m[m] = ((unsigned)d << 16) | (unsigned)p;
    }
}

__global__ void k_classify(const float* __restrict__ y) {
    int b = blockIdx.x * blockDim.x + threadIdx.x;
    if (b >= B_) return;
    int e = 0;
    #pragma unroll
    for (int j = 0; j < E_; j++)
        if (y[b * E_ + j] > 0.5f) e = j;
    int idx = atomicAdd(&g_cnt[e], 1);
    g_nodes[e * B_ + idx] = b;
}

// ---------------- symmetrize U3 (per w,k) and U2 -------------------------
// grid: 84 = 69 (3w x 23k for U3) + 15 (3w x 5k for U2)
__global__ __launch_bounds__(256) void k_sym(
    const float* __restrict__ U3, const float* __restrict__ U2) {
    __shared__ float s[NM_];
    int t = threadIdx.x;
    int bid = blockIdx.x;
    if (bid < 69) {
        int w = bid / P3_, k = bid % P3_;
        for (int i = t; i < NM_; i += 256) s[i] = 0.f;
        __syncthreads();
        for (int idx = t; idx < 4096; idx += 256) {
            int xx = idx >> 8, v = (idx >> 4) & 15, i = idx & 15;
            float val = U3[((((w * L_ + xx) * L_ + v) * L_ + i) * P3_) + k];
            int hi = max(xx, max(v, i));
            int lo = min(xx, min(v, i));
            int mid = xx + v + i - hi - lo;
            int m = Tet(hi) + mid * (mid + 1) / 2 + lo;
            atomicAdd(&s[m], val);
        }
        __syncthreads();
        for (int m = t; m < NM_; m += 256)
            g_U3sym[(w * NM_ + m) * P3_ + k] = s[m];
    } else {
        int b2 = bid - 69;
        int w = b2 / P2_, k = b2 % P2_;
        if (t < NP_) s[t] = 0.f;
        __syncthreads();
        if (t < 256) {
            int xx = t >> 4, v = t & 15;
            float val = U2[((w * L_ + xx) * L_ + v) * P2_ + k];
            int hi = max(xx, v), lo = min(xx, v);
            int p = hi * (hi + 1) / 2 + lo;
            atomicAdd(&s[p], val);
        }
        __syncthreads();
        if (t < NP_)
            g_U2sym[(w * NP_ + t) * P2_ + k] = s[t];
    }
}

// ---------------- coeff GEMM, triple part --------------------------------
// (2448 rows = w*816+m, K=23) @ (23 x 1280 ec).  grid (39 row-tiles, 40 ec-tiles)
__global__ __launch_bounds__(256) void k_coeffA(const float* __restrict__ wmax) {
    __shared__ float us[64][24];
    __shared__ float ws[P3_][32];
    __shared__ float outs[32][65];
    int t = threadIdx.x;
    int row0 = blockIdx.x * 64;
    int ec0 = blockIdx.y * 32;
    int e = ec0 >> 7, c0 = ec0 & 127;

    for (int idx = t; idx < 64 * P3_; idx += 256) {
        int rr = idx / P3_, k = idx % P3_;
        int row = row0 + rr;
        us[rr][k] = (row < EQ_ * NM_) ? g_U3sym[row * P3_ + k] : 0.f;
    }
    for (int idx = t; idx < P3_ * 32; idx += 256) {
        int k = idx >> 5, cc = idx & 31;
        ws[k][cc] = wmax[(e * P3_ + k) * C_ + c0 + cc];
    }
    __syncthreads();

    int cc = t & 31, rg = t >> 5;
    #pragma unroll
    for (int rs = 0; rs < 8; rs++) {
        int rr = rg * 8 + rs;
        float acc = 0.f;
        #pragma unroll
        for (int k = 0; k < P3_; k++) acc += us[rr][k] * ws[k][cc];
        outs[cc][rr] = acc;
    }
    __syncthreads();

    for (int idx = t; idx < 32 * 64; idx += 256) {
        int c2 = idx >> 6, rr = idx & 63;
        int row = row0 + rr;
        if (row < EQ_ * NM_) {
            int w = row / NM_, m = row - w * NM_;
            g_coeff[((size_t)(ec0 + c2) * EQ_ + w) * NF2_ + m] = outs[c2][rr];
        }
    }
}

// ---------------- coeff tail: pairs + linear + zero pad, one thread/output
// outputs: 1280 ec x 3 w x 208 j  (j2 in [0,208) -> feature index 816+j2)
__global__ __launch_bounds__(256) void k_coeffB(
    const float* __restrict__ U1, const float* __restrict__ w2,
    const float* __restrict__ w1) {
    int i = blockIdx.x * 256 + threadIdx.x;
    if (i >= E_ * C_ * EQ_ * 208) return;
    int j2 = i % 208;
    int w  = (i / 208) % EQ_;
    int ec = i / (208 * EQ_);
    int e = ec >> 7, c = ec & 127;
    float s = 0.f;
    if (j2 < NP_) {
        #pragma unroll
        for (int k = 0; k < P2_; k++)
            s += g_U2sym[(w * NP_ + j2) * P2_ + k] * __ldg(&w2[(e * P2_ + k) * C_ + c]);
    } else if (j2 < NP_ + L_) {
        s = __ldg(&U1[w * L_ + (j2 - NP_)]) * __ldg(&w1[e * C_ + c]);
    }
    g_coeff[((size_t)ec * EQ_ + w) * NF2_ + NM_ + j2] = s;
}

// ---------------- main: block per (c,e); 2 warps (a "pair") per node -----
__global__ __launch_bounds__(256, 2) void k_main(
    const float* __restrict__ x, float* __restrict__ out) {
    __shared__ float F[4][NF2_];
    __shared__ unsigned s_tm[NM_];
    __shared__ unsigned s_tp[NP_];
    __shared__ float s_red[4][3];

    int t = threadIdx.x;
    int warp = t >> 5, lane = t & 31;
    int pw = warp >> 1;          // pair id 0..3
    int half = warp & 1;
    int l64 = t & 63;            // lane within pair
    int c = blockIdx.x, e = blockIdx.y;

    // per-lane coefficient registers: feature j = l64 + 64r
    const float* cfb = g_coeff + (size_t)(e * C_ + c) * EQ_ * NF2_;
    float cf0[NCH2_], cf1[NCH2_], cf2[NCH2_];
    #pragma unroll
    for (int r = 0; r < NCH2_; r++) {
        cf0[r] = cfb[0 * NF2_ + l64 + 64 * r];
        cf1[r] = cfb[1 * NF2_ + l64 + 64 * r];
        cf2[r] = cfb[2 * NF2_ + l64 + 64 * r];
    }
    for (int i = t; i < NM_; i += 256) s_tm[i] = g_tab_m[i];
    for (int i = t; i < NP_; i += 256) s_tp[i] = g_tab_pr[i];
    {   // zero the pad region [968,1024) of each pair's feature vector
        int p = t >> 6, j = t & 63;
        if (j < 56) F[p][968 + j] = 0.f;
    }
    __syncthreads();

    #define PBAR() asm volatile("bar.sync %0, 64;" :: "r"(pw + 1) : "memory")

    int nb = g_cnt[e];
    float* Fw = F[pw];
    float* xw = Fw + NM_ + NP_;

    for (int jn = pw; jn < nb; jn += 4) {
        int b = g_nodes[e * B_ + jn];
        // x: both warps write identical values (benign), own-warp visibility via syncwarp
        if (lane < L_) xw[lane] = x[((size_t)b * C_ + c) * L_ + lane];
        __syncwarp();
        // pairs: zp[p] = x_a * x_b   (split over 64 lanes)
        #pragma unroll
        for (int r = 0; r < 3; r++) {
            int p = l64 + 64 * r;
            if (p < NP_) {
                unsigned ab = s_tp[p];
                Fw[NM_ + p] = xw[ab >> 16] * xw[ab & 0xffff];
            }
        }
        PBAR();   // pairs visible across the two warps
        // triples: z[m] = zp[p] * x_d
        #pragma unroll
        for (int r = 0; r < 13; r++) {
            int m = l64 + 64 * r;
            if (m < NM_) {
                unsigned dp = s_tm[m];
                Fw[m] = Fw[NM_ + (dp & 0xffff)] * xw[dp >> 16];
            }
        }
        PBAR();   // full feature vector visible
        // dot: out[w] = sum_j coeff[w][j] * F[j]
        float a0 = 0.f, a1 = 0.f, a2 = 0.f;
        #pragma unroll
        for (int r = 0; r < NCH2_; r++) {
            float f = Fw[l64 + 64 * r];
            a0 += f * cf0[r];
            a1 += f * cf1[r];
            a2 += f * cf2[r];
        }
        #pragma unroll
        for (int msk = 16; msk >= 1; msk >>= 1) {
            a0 += __shfl_xor_sync(0xffffffffu, a0, msk);
            a1 += __shfl_xor_sync(0xffffffffu, a1, msk);
            a2 += __shfl_xor_sync(0xffffffffu, a2, msk);
        }
        if (half == 1 && lane == 0) {
            s_red[pw][0] = a0; s_red[pw][1] = a1; s_red[pw][2] = a2;
        }
        PBAR();   // exchange halves; also protects F overwrite next iter
        if (half == 0 && lane == 0) {
            float* o = out + ((size_t)b * C_ + c) * EQ_;
            o[0] = a0 + s_red[pw][0];
            o[1] = a1 + s_red[pw][1];
            o[2] = a2 + s_red[pw][2];
        }
    }
    #undef PBAR
}

extern "C" void kernel_launch(void* const* d_in, const int* in_sizes, int n_in,
                              void* d_out, int out_size) {
    const float* x    = (const float*)d_in[0];
    const float* y    = (const float*)d_in[1];
    const float* U3   = (const float*)d_in[2];
    const float* U2   = (const float*)d_in[3];
    const float* U1   = (const float*)d_in[4];
    const float* wmax = (const float*)d_in[5];
    const float* w2   = (const float*)d_in[6];
    const float* w1   = (const float*)d_in[7];
    float* out = (float*)d_out;

    k_setup<<<1, 256>>>();
    k_classify<<<4, 256>>>(y);
    k_sym<<<84, 256>>>(U3, U2);
    k_coeffA<<<dim3(39, 40), 256>>>(wmax);
    k_coeffB<<<3120, 256>>>(U1, w2, w1);
    k_main<<<dim3(C_, E_), 256>>>(x, out);
}

// round 6
// speedup vs baseline: 6.7680x; 1.7908x over previous
#include <cuda_runtime.h>

#define B_   1024
#define C_   128
#define L_   16
#define EQ_  3
#define E_   10
#define P3_  23
#define P2_  5
#define NP_  136     // symmetric pairs (a<=b), global pair id
#define NM_  816     // symmetric triples
#define NDS_ 448     // dual-slots (412 real, padded)
#define NJ3_ 896     // 2*NDS_  : triple-region coeff positions
#define NJ2_ 192     // pair/x-region positions (136 pairs + 16 x + 40 pad)
#define NF_  1088    // NJ3_ + NJ2_
#define CW_  (EQ_*NF_)   // 3264 coeff floats per (e,c)

// Scratch (__device__ globals — no allocation)
__device__ float g_U3sym[EQ_ * NM_ * P3_];
__device__ float g_U2sym[EQ_ * NP_ * P2_];
__device__ float g_coeff[(size_t)E_ * C_ * CW_];     // 16.7 MB
__device__ unsigned short g_dcode[NDS_];             // p | d<<8  (p even)
__device__ unsigned short g_pcode[NJ2_];             // a | b<<4 | isx<<8 | sts<<9
__device__ unsigned short g_ds_feat[NJ3_];           // m or 0xFFFF
__device__ int g_cnt[E_];
__device__ int g_nodes[E_ * B_];

__host__ __device__ __forceinline__ int Tet(int d) { return d * (d + 1) * (d + 2) / 6; }

// ---------------- setup: tables + counters -------------------------------
__global__ void k_setup() {
    int t = threadIdx.x;
    if (t < E_) g_cnt[t] = 0;
    // pair/x region codes
    for (int j2 = t; j2 < NJ2_; j2 += 256) {
        unsigned code;
        if (j2 < NP_) {
            int b = 0;
            while ((b + 1) * (b + 2) / 2 <= j2) b++;
            int a = j2 - b * (b + 1) / 2;
            code = (unsigned)a | ((unsigned)b << 4) | (1u << 9);   // sts
        } else if (j2 < NP_ + L_) {
            code = (unsigned)(j2 - NP_) | (1u << 8);               // isx
        } else {
            code = (1u << 8);                                      // dummy (coeff 0)
        }
        g_pcode[j2] = (unsigned short)code;
    }
    // dual-slot tables: duals grouped by d, p ascending even
    if (t < 16) {
        int d = t;
        int off = 0;
        for (int d2 = 0; d2 < d; d2++) { int P = (d2 + 1) * (d2 + 2) / 2; off += (P + 1) >> 1; }
        int P = (d + 1) * (d + 2) / 2;
        for (int p = 0; p < P; p += 2) {
            int ds = off + (p >> 1);
            g_dcode[ds] = (unsigned short)(p | (d << 8));
            g_ds_feat[2 * ds] = (unsigned short)(Tet(d) + p);
            g_ds_feat[2 * ds + 1] = (p + 1 < P) ? (unsigned short)(Tet(d) + p + 1) : (unsigned short)0xFFFF;
        }
    }
    if (t == 16) {
        for (int ds = 412; ds < NDS_; ds++) {
            g_dcode[ds] = 0;
            g_ds_feat[2 * ds] = 0xFFFF;
            g_ds_feat[2 * ds + 1] = 0xFFFF;
        }
    }
}

__global__ void k_classify(const float* __restrict__ y) {
    int b = blockIdx.x * blockDim.x + threadIdx.x;
    if (b >= B_) return;
    int e = 0;
    #pragma unroll
    for (int j = 0; j < E_; j++)
        if (y[b * E_ + j] > 0.5f) e = j;
    int idx = atomicAdd(&g_cnt[e], 1);
    g_nodes[e * B_ + idx] = b;
}

// ---------------- symmetrize U3 / U2 -------------------------------------
__global__ __launch_bounds__(256) void k_sym(
    const float* __restrict__ U3, const float* __restrict__ U2) {
    __shared__ float s[NM_];
    int t = threadIdx.x;
    int bid = blockIdx.x;
    if (bid < 69) {
        int w = bid / P3_, k = bid % P3_;
        for (int i = t; i < NM_; i += 256) s[i] = 0.f;
        __syncthreads();
        for (int idx = t; idx < 4096; idx += 256) {
            int xx = idx >> 8, v = (idx >> 4) & 15, i = idx & 15;
            float val = U3[((((w * L_ + xx) * L_ + v) * L_ + i) * P3_) + k];
            int hi = max(xx, max(v, i));
            int lo = min(xx, min(v, i));
            int mid = xx + v + i - hi - lo;
            int m = Tet(hi) + mid * (mid + 1) / 2 + lo;
            atomicAdd(&s[m], val);
        }
        __syncthreads();
        for (int m = t; m < NM_; m += 256)
            g_U3sym[(w * NM_ + m) * P3_ + k] = s[m];
    } else {
        int b2 = bid - 69;
        int w = b2 / P2_, k = b2 % P2_;
        if (t < NP_) s[t] = 0.f;
        __syncthreads();
        {
            int xx = t >> 4, v = t & 15;
            float val = U2[((w * L_ + xx) * L_ + v) * P2_ + k];
            int hi = max(xx, v), lo = min(xx, v);
            int p = hi * (hi + 1) / 2 + lo;
            atomicAdd(&s[p], val);
        }
        __syncthreads();
        if (t < NP_)
            g_U2sym[(w * NP_ + t) * P2_ + k] = s[t];
    }
}

// ---------------- coeff GEMM, triple region ------------------------------
// rows j = w*896 + jj (jj -> feature m via g_ds_feat), K=23, cols = 1280 ec.
// grid (42 row-tiles of 64, 20 ec-tiles of 64), 256 threads.
__global__ __launch_bounds__(256) void k_coeffA(const float* __restrict__ wmax) {
    __shared__ float us[64][24];
    __shared__ float ws[P3_][64];
    __shared__ float outs[64][65];
    int t = threadIdx.x;
    int row0 = blockIdx.x * 64;
    int ec0 = blockIdx.y * 64;
    int e = ec0 >> 7, c0 = ec0 & 127;   // 64-wide ec tile stays in one e (128%64==0)

    for (int idx = t; idx < 64 * P3_; idx += 256) {
        int rr = idx / P3_, k = idx % P3_;
        int row = row0 + rr;
        float v = 0.f;
        if (row < EQ_ * NJ3_) {
            int w = row / NJ3_, jj = row - w * NJ3_;
            int m = g_ds_feat[jj];
            if (m != 0xFFFF) v = g_U3sym[(w * NM_ + m) * P3_ + k];
        }
        us[rr][k] = v;
    }
    for (int idx = t; idx < P3_ * 64; idx += 256) {
        int k = idx >> 6, cc = idx & 63;
        ws[k][cc] = wmax[(e * P3_ + k) * C_ + c0 + cc];
    }
    __syncthreads();

    int cc = t & 63, rg = t >> 6;
    #pragma unroll
    for (int rs = 0; rs < 16; rs++) {
        int rr = rg * 16 + rs;
        float acc = 0.f;
        #pragma unroll
        for (int k = 0; k < P3_; k++) acc += us[rr][k] * ws[k][cc];
        outs[cc][rr] = acc;
    }
    __syncthreads();

    for (int idx = t; idx < 64 * 64; idx += 256) {
        int c2 = idx >> 6, rr = idx & 63;
        int row = row0 + rr;
        if (row < EQ_ * NJ3_) {
            int w = row / NJ3_, jj = row - w * NJ3_;
            g_coeff[(size_t)(ec0 + c2) * CW_ + w * NF_ + jj] = outs[c2][rr];
        }
    }
}

// ---------------- coeff tail: pair/x region ------------------------------
__global__ __launch_bounds__(256) void k_coeffB(
    const float* __restrict__ U1, const float* __restrict__ w2,
    const float* __restrict__ w1) {
    int i = blockIdx.x * 256 + threadIdx.x;
    if (i >= E_ * C_ * EQ_ * NJ2_) return;
    int j2 = i % NJ2_;
    int w  = (i / NJ2_) % EQ_;
    int ec = i / (NJ2_ * EQ_);
    int e = ec >> 7, c = ec & 127;
    float s = 0.f;
    if (j2 < NP_) {
        #pragma unroll
        for (int k = 0; k < P2_; k++)
            s += g_U2sym[(w * NP_ + j2) * P2_ + k] * __ldg(&w2[(e * P2_ + k) * C_ + c]);
    } else if (j2 < NP_ + L_) {
        s = __ldg(&U1[w * L_ + (j2 - NP_)]) * __ldg(&w1[e * C_ + c]);
    }
    g_coeff[(size_t)ec * CW_ + w * NF_ + NJ3_ + j2] = s;
}

// ---------------- main: block per (c,e); 2 warps per node ----------------
__global__ __launch_bounds__(256, 2) void k_main(
    const float* __restrict__ x, float* __restrict__ out) {
    __shared__ __align__(16) float zp[4][160];   // [0,136) zp ; [144,160) xw
    __shared__ float s_red[4][3];

    int t = threadIdx.x;
    int warp = t >> 5, lane = t & 31;
    int pw = warp >> 1;
    int half = warp & 1;
    int c = blockIdx.x, e = blockIdx.y;

    const float* cfb = g_coeff + (size_t)(e * C_ + c) * CW_;

    // dual-step coefficients (float2 per step)
    float2 cd0[7], cd1[7], cd2[7];
    #pragma unroll
    for (int r = 0; r < 7; r++) {
        int j = ((half * 7 + r) * 32 + lane) * 2;
        cd0[r] = *(const float2*)(cfb + 0 * NF_ + j);
        cd1[r] = *(const float2*)(cfb + 1 * NF_ + j);
        cd2[r] = *(const float2*)(cfb + 2 * NF_ + j);
    }
    // pair-region coefficients
    float cp0[3], cp1[3], cp2[3];
    unsigned pcode[3];
    #pragma unroll
    for (int r = 0; r < 3; r++) {
        int j2 = (half * 3 + r) * 32 + lane;
        cp0[r] = cfb[0 * NF_ + NJ3_ + j2];
        cp1[r] = cfb[1 * NF_ + NJ3_ + j2];
        cp2[r] = cfb[2 * NF_ + NJ3_ + j2];
        pcode[r] = g_pcode[j2];
    }
    unsigned dcode[7];
    #pragma unroll
    for (int r = 0; r < 7; r++)
        dcode[r] = g_dcode[(half * 7 + r) * 32 + lane];

    float* zpw = zp[pw];
    float* xw  = zpw + 144;

    int nb = g_cnt[e];
    int jn = pw;
    int bnext = -1; float xv = 0.f;
    if (jn < nb) {
        bnext = g_nodes[e * B_ + jn];
        if (lane < L_) xv = __ldg(&x[((size_t)bnext * C_ + c) * L_ + lane]);
    }

    #define PBAR() asm volatile("bar.sync %0, 64;" :: "r"(pw + 1) : "memory")

    for (; jn < nb; jn += 4) {
        int bcur = bnext;
        if (lane < L_) xw[lane] = xv;
        __syncwarp();
        // start next-node prefetch (index first)
        int jn2 = jn + 4;
        bnext = (jn2 < nb) ? g_nodes[e * B_ + jn2] : -1;

        // pair/x region: compute value, contribute to dot, store zp
        float a0 = 0.f, a1 = 0.f, a2 = 0.f;
        #pragma unroll
        for (int r = 0; r < 3; r++) {
            unsigned cc = pcode[r];
            float va = xw[cc & 15];
            float vb = xw[(cc >> 4) & 15];
            float val = (cc & 256u) ? va : va * vb;
            if (cc & 512u) zpw[(half * 3 + r) * 32 + lane] = val;
            a0 += cp0[r] * val;
            a1 += cp1[r] * val;
            a2 += cp2[r] * val;
        }
        // x prefetch (hide DRAM latency behind the dual steps)
        if (bnext >= 0) {
            if (lane < L_) xv = __ldg(&x[((size_t)bnext * C_ + c) * L_ + lane]);
        } else xv = 0.f;

        PBAR();   // zp visible across the warp pair

        // fused triple dot: 7 dual steps
        #pragma unroll
        for (int r = 0; r < 7; r++) {
            unsigned cc = dcode[r];
            int p = cc & 255, d = cc >> 8;
            float2 z = *(const float2*)(zpw + p);
            float xd = xw[d];
            float t0 = z.x * xd, t1 = z.y * xd;
            a0 += cd0[r].x * t0 + cd0[r].y * t1;
            a1 += cd1[r].x * t0 + cd1[r].y * t1;
            a2 += cd2[r].x * t0 + cd2[r].y * t1;
        }

        // warp reduce
        #pragma unroll
        for (int msk = 16; msk >= 1; msk >>= 1) {
            a0 += __shfl_xor_sync(0xffffffffu, a0, msk);
            a1 += __shfl_xor_sync(0xffffffffu, a1, msk);
            a2 += __shfl_xor_sync(0xffffffffu, a2, msk);
        }
        if (half == 1 && lane == 0) {
            s_red[pw][0] = a0; s_red[pw][1] = a1; s_red[pw][2] = a2;
        }
        PBAR();   // exchange halves; also protects zp/xw overwrite next iter
        if (half == 0 && lane == 0) {
            float* o = out + ((size_t)bcur * C_ + c) * EQ_;
            o[0] = a0 + s_red[pw][0];
            o[1] = a1 + s_red[pw][1];
            o[2] = a2 + s_red[pw][2];
        }
    }
    #undef PBAR
}

extern "C" void kernel_launch(void* const* d_in, const int* in_sizes, int n_in,
                              void* d_out, int out_size) {
    const float* x    = (const float*)d_in[0];
    const float* y    = (const float*)d_in[1];
    const float* U3   = (const float*)d_in[2];
    const float* U2   = (const float*)d_in[3];
    const float* U1   = (const float*)d_in[4];
    const float* wmax = (const float*)d_in[5];
    const float* w2   = (const float*)d_in[6];
    const float* w1   = (const float*)d_in[7];
    float* out = (float*)d_out;

    k_setup<<<1, 256>>>();
    k_classify<<<4, 256>>>(y);
    k_sym<<<84, 256>>>(U3, U2);
    k_coeffA<<<dim3(42, 20), 256>>>(wmax);
    k_coeffB<<<2880, 256>>>(U1, w2, w1);
    k_main<<<dim3(C_, E_), 256>>>(x, out);
}

// round 7
// speedup vs baseline: 7.1387x; 1.0548x over previous
#include <cuda_runtime.h>

#define B_   1024
#define C_   128
#define L_   16
#define EQ_  3
#define E_   10
#define P3_  23
#define P2_  5
#define NP_  136     // symmetric pairs (a<=b)
#define NM_  816     // symmetric triples
#define NDS_ 448     // dual-slots (412 real, padded)
#define NJ3_ 896     // 2*NDS_
#define NJ2_ 192     // pair/x region (136 pairs + 16 x + 40 pad)
#define NF_  1088    // NJ3_ + NJ2_
#define CW_  (EQ_*NF_)

typedef unsigned long long ull;

// Scratch (__device__ globals — no allocation)
__device__ float g_U3sym[EQ_ * NM_ * P3_];
__device__ float g_U2sym[EQ_ * NP_ * P2_];
__device__ __align__(16) float g_coeff[(size_t)E_ * C_ * CW_];   // 16.7 MB
__device__ unsigned short g_dcode[NDS_];             // p | d<<8  (p even)
__device__ unsigned short g_pcode[NJ2_];             // a | b<<4 | isx<<8
__device__ unsigned short g_ds_feat[NJ3_];           // m or 0xFFFF
__device__ int g_cnt[E_];
__device__ int g_nodes[E_ * B_];

__host__ __device__ __forceinline__ int Tet(int d) { return d * (d + 1) * (d + 2) / 6; }

// ---- asm helpers --------------------------------------------------------
__device__ __forceinline__ float lds_f(unsigned a) {
    float v; asm volatile("ld.shared.f32 %0, [%1];" : "=f"(v) : "r"(a)); return v;
}
__device__ __forceinline__ ull lds_b64(unsigned a) {
    ull v; asm volatile("ld.shared.b64 %0, [%1];" : "=l"(v) : "r"(a)); return v;
}
__device__ __forceinline__ void sts_f(unsigned a, float v) {
    asm volatile("st.shared.f32 [%0], %1;" :: "r"(a), "f"(v));
}
__device__ __forceinline__ ull pack2(float lo, float hi) {
    ull d; asm("mov.b64 %0, {%1, %2};" : "=l"(d) : "f"(lo), "f"(hi)); return d;
}
__device__ __forceinline__ void unpack2(float& lo, float& hi, ull v) {
    asm("mov.b64 {%0, %1}, %2;" : "=f"(lo), "=f"(hi) : "l"(v));
}
__device__ __forceinline__ ull mul2(ull a, ull b) {
    ull d; asm("mul.rn.f32x2 %0, %1, %2;" : "=l"(d) : "l"(a), "l"(b)); return d;
}
__device__ __forceinline__ ull fma2(ull a, ull b, ull c) {
    ull d; asm("fma.rn.f32x2 %0, %1, %2, %3;" : "=l"(d) : "l"(a), "l"(b), "l"(c)); return d;
}

// ---------------- launch 1: tables + classify + symmetrize ---------------
// grid 86 x 1024: bid 0 = tables, bid 1 = classify, bid 2..85 = sym
__global__ __launch_bounds__(1024) void k_prep(
    const float* __restrict__ y, const float* __restrict__ U3,
    const float* __restrict__ U2) {
    __shared__ float s[NM_];
    __shared__ int wcnt[32][E_];
    int t = threadIdx.x;
    int bid = blockIdx.x;

    if (bid == 0) {
        for (int j2 = t; j2 < NJ2_; j2 += 1024) {
            unsigned code;
            if (j2 < NP_) {
                int b = 0;
                while ((b + 1) * (b + 2) / 2 <= j2) b++;
                int a = j2 - b * (b + 1) / 2;
                code = (unsigned)a | ((unsigned)b << 4);
            } else if (j2 < NP_ + L_) {
                code = (unsigned)(j2 - NP_) | (1u << 8);
            } else {
                code = (1u << 8);
            }
            g_pcode[j2] = (unsigned short)code;
        }
        if (t < 16) {
            int d = t;
            int off = 0;
            for (int d2 = 0; d2 < d; d2++) { int P = (d2 + 1) * (d2 + 2) / 2; off += (P + 1) >> 1; }
            int P = (d + 1) * (d + 2) / 2;
            for (int p = 0; p < P; p += 2) {
                int ds = off + (p >> 1);
                g_dcode[ds] = (unsigned short)(p | (d << 8));
                g_ds_feat[2 * ds] = (unsigned short)(Tet(d) + p);
                g_ds_feat[2 * ds + 1] = (p + 1 < P) ? (unsigned short)(Tet(d) + p + 1) : (unsigned short)0xFFFF;
            }
        }
        if (t == 16) {
            for (int ds = 412; ds < NDS_; ds++) {
                g_dcode[ds] = 0;
                g_ds_feat[2 * ds] = 0xFFFF;
                g_ds_feat[2 * ds + 1] = 0xFFFF;
            }
        }
    } else if (bid == 1) {
        // atomic-free deterministic classify: 1024 threads = B_
        int b = t;
        int e = 0;
        #pragma unroll
        for (int j = 0; j < E_; j++)
            if (y[b * E_ + j] > 0.5f) e = j;
        int warp = t >> 5, lane = t & 31;
        unsigned m = __match_any_sync(0xffffffffu, e);
        int rank = __popc(m & ((1u << lane) - 1u));
        int ldr = __ffs(m) - 1;
        if (t < 32 * E_) ((int*)wcnt)[t] = 0;
        __syncthreads();
        if (lane == ldr) wcnt[warp][e] = __popc(m);
        __syncthreads();
        int off = 0;
        for (int w = 0; w < warp; w++) off += wcnt[w][e];
        g_nodes[e * B_ + off + rank] = b;
        if (t < E_) {
            int tot = 0;
            #pragma unroll
            for (int w = 0; w < 32; w++) tot += wcnt[w][t];
            g_cnt[t] = tot;
        }
    } else if (bid < 71) {        // 69 U3-sym blocks
        int b2 = bid - 2;
        int w = b2 / P3_, k = b2 % P3_;
        for (int i = t; i < NM_; i += 1024) s[i] = 0.f;
        __syncthreads();
        for (int idx = t; idx < 4096; idx += 1024) {
            int xx = idx >> 8, v = (idx >> 4) & 15, i = idx & 15;
            float val = U3[((((w * L_ + xx) * L_ + v) * L_ + i) * P3_) + k];
            int hi = max(xx, max(v, i));
            int lo = min(xx, min(v, i));
            int mid = xx + v + i - hi - lo;
            int mm = Tet(hi) + mid * (mid + 1) / 2 + lo;
            atomicAdd(&s[mm], val);
        }
        __syncthreads();
        for (int mm = t; mm < NM_; mm += 1024)
            g_U3sym[(w * NM_ + mm) * P3_ + k] = s[mm];
    } else if (bid < 86) {        // 15 U2-sym blocks
        int b2 = bid - 71;
        int w = b2 / P2_, k = b2 % P2_;
        if (t < NP_) s[t] = 0.f;
        __syncthreads();
        if (t < 256) {
            int xx = t >> 4, v = t & 15;
            float val = U2[((w * L_ + xx) * L_ + v) * P2_ + k];
            int hi = max(xx, v), lo = min(xx, v);
            int p = hi * (hi + 1) / 2 + lo;
            atomicAdd(&s[p], val);
        }
        __syncthreads();
        if (t < NP_)
            g_U2sym[(w * NP_ + t) * P2_ + k] = s[t];
    }
}

// ---------------- launch 2: coefficient build ----------------------------
// grid 3720 x 256: bid < 840 -> triple-region GEMM tile; else pair/x tail
__global__ __launch_bounds__(256) void k_coeff(
    const float* __restrict__ wmax, const float* __restrict__ U1,
    const float* __restrict__ w2, const float* __restrict__ w1) {
    __shared__ float us[64][24];
    __shared__ float ws[P3_][64];
    __shared__ float outs[64][65];
    int t = threadIdx.x;
    int bid = blockIdx.x;

    if (bid < 840) {
        int row0 = (bid % 42) * 64;
        int ec0 = (bid / 42) * 64;
        int e = ec0 >> 7, c0 = ec0 & 127;

        for (int idx = t; idx < 64 * P3_; idx += 256) {
            int rr = idx / P3_, k = idx % P3_;
            int row = row0 + rr;
            float v = 0.f;
            if (row < EQ_ * NJ3_) {
                int w = row / NJ3_, jj = row - w * NJ3_;
                int m = g_ds_feat[jj];
                if (m != 0xFFFF) v = g_U3sym[(w * NM_ + m) * P3_ + k];
            }
            us[rr][k] = v;
        }
        for (int idx = t; idx < P3_ * 64; idx += 256) {
            int k = idx >> 6, cc = idx & 63;
            ws[k][cc] = wmax[(e * P3_ + k) * C_ + c0 + cc];
        }
        __syncthreads();

        int cc = t & 63, rg = t >> 6;
        float wreg[P3_];
        #pragma unroll
        for (int k = 0; k < P3_; k++) wreg[k] = ws[k][cc];
        #pragma unroll
        for (int rs = 0; rs < 16; rs++) {
            int rr = rg * 16 + rs;
            float acc = 0.f;
            #pragma unroll
            for (int k = 0; k < P3_; k++) acc += us[rr][k] * wreg[k];
            outs[cc][rr] = acc;
        }
        __syncthreads();

        for (int idx = t; idx < 64 * 64; idx += 256) {
            int c2 = idx >> 6, rr = idx & 63;
            int row = row0 + rr;
            if (row < EQ_ * NJ3_) {
                int w = row / NJ3_, jj = row - w * NJ3_;
                g_coeff[(size_t)(ec0 + c2) * CW_ + w * NF_ + jj] = outs[c2][rr];
            }
        }
    } else {
        int i = (bid - 840) * 256 + t;     // exactly 2880*256 = 737280 outputs
        int j2 = i % NJ2_;
        int w  = (i / NJ2_) % EQ_;
        int ec = i / (NJ2_ * EQ_);
        int e = ec >> 7, c = ec & 127;
        float sv = 0.f;
        if (j2 < NP_) {
            #pragma unroll
            for (int k = 0; k < P2_; k++)
                sv += g_U2sym[(w * NP_ + j2) * P2_ + k] * __ldg(&w2[(e * P2_ + k) * C_ + c]);
        } else if (j2 < NP_ + L_) {
            sv = __ldg(&U1[w * L_ + (j2 - NP_)]) * __ldg(&w1[e * C_ + c]);
        }
        g_coeff[(size_t)ec * CW_ + w * NF_ + NJ3_ + j2] = sv;
    }
}

// ---------------- launch 3: main — block per (c,e); 2 warps per node -----
// smem per pair: [0,136) zp ; [144,160) xw ; [160] = 1.0f ; [161] dummy sink
__global__ __launch_bounds__(256, 2) void k_main(
    const float* __restrict__ x, float* __restrict__ out) {
    __shared__ __align__(16) float zp[4][168];
    __shared__ float s_red[4][3];

    int t = threadIdx.x;
    int warp = t >> 5, lane = t & 31;
    int pw = warp >> 1;
    int half = warp & 1;
    int c = blockIdx.x, e = blockIdx.y;

    const float* cfb = g_coeff + (size_t)(e * C_ + c) * CW_;

    float* zpw = zp[pw];
    unsigned zbase = (unsigned)__cvta_generic_to_shared(zpw);
    unsigned xbase = zbase + 144 * 4;

    // packed dual-step coefficients + precomputed smem addresses
    ull cd0[7], cd1[7], cd2[7];
    unsigned zsa[7], xsa[7];
    #pragma unroll
    for (int r = 0; r < 7; r++) {
        int ds = (half * 7 + r) * 32 + lane;
        int j = ds * 2;
        cd0[r] = *(const ull*)(cfb + 0 * NF_ + j);
        cd1[r] = *(const ull*)(cfb + 1 * NF_ + j);
        cd2[r] = *(const ull*)(cfb + 2 * NF_ + j);
        unsigned cc = g_dcode[ds];
        zsa[r] = zbase + (cc & 255u) * 4u;
        xsa[r] = xbase + (cc >> 8) * 4u;
    }
    // pair-region coefficients + addresses (branchless: isx -> multiply by 1.0f slot)
    float cp0[3], cp1[3], cp2[3];
    unsigned pa[3], pb[3], psta[3];
    #pragma unroll
    for (int r = 0; r < 3; r++) {
        int j2 = (half * 3 + r) * 32 + lane;
        cp0[r] = cfb[0 * NF_ + NJ3_ + j2];
        cp1[r] = cfb[1 * NF_ + NJ3_ + j2];
        cp2[r] = cfb[2 * NF_ + NJ3_ + j2];
        unsigned cc = g_pcode[j2];
        pa[r] = xbase + (cc & 15u) * 4u;
        pb[r] = (cc & 256u) ? (zbase + 160u * 4u) : (xbase + ((cc >> 4) & 15u) * 4u);
        psta[r] = (j2 < NP_) ? (zbase + (unsigned)j2 * 4u) : (zbase + 161u * 4u);
    }
    sts_f(zbase + 160u * 4u, 1.0f);   // the constant-one slot

    int nb = g_cnt[e];
    int jn = pw;
    int bnext = -1; float xv = 0.f;
    if (jn < nb) {
        bnext = g_nodes[e * B_ + jn];
        if (lane < L_) xv = __ldg(&x[((size_t)bnext * C_ + c) * L_ + lane]);
    }

    #define PBAR() asm volatile("bar.sync %0, 64;" :: "r"(pw + 1) : "memory")

    for (; jn < nb; jn += 4) {
        int bcur = bnext;
        if (lane < L_) sts_f(xbase + lane * 4u, xv);
        __syncwarp();
        int jn2 = jn + 4;
        bnext = (jn2 < nb) ? g_nodes[e * B_ + jn2] : -1;

        // pair/x region: value -> dot contribution + zp store
        float s0 = 0.f, s1 = 0.f, s2 = 0.f;
        #pragma unroll
        for (int r = 0; r < 3; r++) {
            float va = lds_f(pa[r]);
            float vb = lds_f(pb[r]);
            float val = va * vb;
            sts_f(psta[r], val);
            s0 = fmaf(cp0[r], val, s0);
            s1 = fmaf(cp1[r], val, s1);
            s2 = fmaf(cp2[r], val, s2);
        }
        // next-node x prefetch (hidden behind dual steps)
        if (bnext >= 0) {
            if (lane < L_) xv = __ldg(&x[((size_t)bnext * C_ + c) * L_ + lane]);
        } else xv = 0.f;

        PBAR();   // zp visible across the warp pair

        // fused triple dot: 7 dual steps, packed f32x2
        ull a0p = 0ull, a1p = 0ull, a2p = 0ull;
        #pragma unroll
        for (int r = 0; r < 7; r++) {
            ull z = lds_b64(zsa[r]);
            float xd = lds_f(xsa[r]);
            ull xdp = pack2(xd, xd);
            ull tp = mul2(z, xdp);
            a0p = fma2(cd0[r], tp, a0p);
            a1p = fma2(cd1[r], tp, a1p);
            a2p = fma2(cd2[r], tp, a2p);
        }
        float lo, hi;
        unpack2(lo, hi, a0p); float a0 = s0 + lo + hi;
        unpack2(lo, hi, a1p); float a1 = s1 + lo + hi;
        unpack2(lo, hi, a2p); float a2 = s2 + lo + hi;

        // warp reduce
        #pragma unroll
        for (int msk = 16; msk >= 1; msk >>= 1) {
            a0 += __shfl_xor_sync(0xffffffffu, a0, msk);
            a1 += __shfl_xor_sync(0xffffffffu, a1, msk);
            a2 += __shfl_xor_sync(0xffffffffu, a2, msk);
        }
        if (half == 1 && lane == 0) {
            s_red[pw][0] = a0; s_red[pw][1] = a1; s_red[pw][2] = a2;
        }
        PBAR();   // exchange halves; also protects zp/xw overwrite next iter
        if (half == 0 && lane == 0) {
            float* o = out + ((size_t)bcur * C_ + c) * EQ_;
            o[0] = a0 + s_red[pw][0];
            o[1] = a1 + s_red[pw][1];
            o[2] = a2 + s_red[pw][2];
        }
    }
    #undef PBAR
}

extern "C" void kernel_launch(void* const* d_in, const int* in_sizes, int n_in,
                              void* d_out, int out_size) {
    const float* x    = (const float*)d_in[0];
    const float* y    = (const float*)d_in[1];
    const float* U3   = (const float*)d_in[2];
    const float* U2   = (const float*)d_in[3];
    const float* U1   = (const float*)d_in[4];
    const float* wmax = (const float*)d_in[5];
    const float* w2   = (const float*)d_in[6];
    const float* w1   = (const float*)d_in[7];
    float* out = (float*)d_out;

    k_prep<<<86, 1024>>>(y, U3, U2);
    k_coeff<<<3720, 256>>>(wmax, U1, w2, w1);
    k_main<<<dim3(C_, E_), 256>>>(x, out);
}

// round 9
// speedup vs baseline: 7.7682x; 1.0882x over previous
#include <cuda_runtime.h>

#define B_   1024
#define C_   128
#define L_   16
#define EQ_  3
#define E_   10
#define P3_  23
#define P2_  5
#define NP_  136     // symmetric pairs (a<=b)
#define NM_  816     // symmetric triples
#define NDS_ 448     // dual-slots (412 real, padded)
#define NJ3_ 896     // 2*NDS_
#define NJ2_ 192     // pair/x region (136 pairs + 16 x + 40 pad)
#define NF_  1088    // NJ3_ + NJ2_
#define CW_  (EQ_*NF_)
#define ZSTR_ 176    // floats per zp buffer; B buffer at byte offset +704

typedef unsigned long long ull;

// Scratch (__device__ globals — no allocation)
__device__ float g_U3sym[EQ_ * NM_ * P3_];
__device__ float g_U2sym[EQ_ * NP_ * P2_];
__device__ __align__(16) float g_coeff[(size_t)E_ * C_ * CW_];   // 16.7 MB
__device__ unsigned short g_dcode[NDS_];             // p | d<<8  (p even)
__device__ unsigned short g_pcode[NJ2_];             // a | b<<4 | isx<<8
__device__ unsigned short g_ds_feat[NJ3_];           // m or 0xFFFF
__device__ int g_cnt[E_];
__device__ int g_nodes[E_ * B_];

__host__ __device__ __forceinline__ int Tet(int d) { return d * (d + 1) * (d + 2) / 6; }

// ---- asm helpers --------------------------------------------------------
__device__ __forceinline__ ull lds_b64(unsigned a) {
    ull v; asm volatile("ld.shared.b64 %0, [%1];" : "=l"(v) : "r"(a)); return v;
}
__device__ __forceinline__ ull lds_b64_B(unsigned a) {   // +704: B buffer
    ull v; asm volatile("ld.shared.b64 %0, [%1+704];" : "=l"(v) : "r"(a)); return v;
}
__device__ __forceinline__ void sts_f(unsigned a, float v) {
    asm volatile("st.shared.f32 [%0], %1;" :: "r"(a), "f"(v));
}
__device__ __forceinline__ void sts_f_B(unsigned a, float v) {
    asm volatile("st.shared.f32 [%0+704], %1;" :: "r"(a), "f"(v));
}
__device__ __forceinline__ ull pack2(float lo, float hi) {
    ull d; asm("mov.b64 %0, {%1, %2};" : "=l"(d) : "f"(lo), "f"(hi)); return d;
}
__device__ __forceinline__ void unpack2(float& lo, float& hi, ull v) {
    asm("mov.b64 {%0, %1}, %2;" : "=f"(lo), "=f"(hi) : "l"(v));
}
__device__ __forceinline__ ull mul2(ull a, ull b) {
    ull d; asm("mul.rn.f32x2 %0, %1, %2;" : "=l"(d) : "l"(a), "l"(b)); return d;
}
__device__ __forceinline__ ull fma2(ull a, ull b, ull c) {
    ull d; asm("fma.rn.f32x2 %0, %1, %2, %3;" : "=l"(d) : "l"(a), "l"(b), "l"(c)); return d;
}

// ---------------- launch 1: tables + classify + symmetrize ---------------
// grid 86 x 1024: bid 0 = tables, bid 1 = classify, bid 2..85 = sym
__global__ __launch_bounds__(1024) void k_prep(
    const float* __restrict__ y, const float* __restrict__ U3,
    const float* __restrict__ U2) {
    __shared__ float s[NM_];
    __shared__ int wcnt[32][E_];
    int t = threadIdx.x;
    int bid = blockIdx.x;

    if (bid == 0) {
        for (int j2 = t; j2 < NJ2_; j2 += 1024) {
            unsigned code;
            if (j2 < NP_) {
                int b = 0;
                while ((b + 1) * (b + 2) / 2 <= j2) b++;
                int a = j2 - b * (b + 1) / 2;
                code = (unsigned)a | ((unsigned)b << 4);
            } else if (j2 < NP_ + L_) {
                code = (unsigned)(j2 - NP_) | (1u << 8);
            } else {
                code = (1u << 8);
            }
            g_pcode[j2] = (unsigned short)code;
        }
        if (t < 16) {
            int d = t;
            int off = 0;
            for (int d2 = 0; d2 < d; d2++) { int P = (d2 + 1) * (d2 + 2) / 2; off += (P + 1) >> 1; }
            int P = (d + 1) * (d + 2) / 2;
            for (int p = 0; p < P; p += 2) {
                int ds = off + (p >> 1);
                g_dcode[ds] = (unsigned short)(p | (d << 8));
                g_ds_feat[2 * ds] = (unsigned short)(Tet(d) + p);
                g_ds_feat[2 * ds + 1] = (p + 1 < P) ? (unsigned short)(Tet(d) + p + 1) : (unsigned short)0xFFFF;
            }
        }
        if (t == 16) {
            for (int ds = 412; ds < NDS_; ds++) {
                g_dcode[ds] = 0;
                g_ds_feat[2 * ds] = 0xFFFF;
                g_ds_feat[2 * ds + 1] = 0xFFFF;
            }
        }
    } else if (bid == 1) {
        // atomic-free deterministic classify: 1024 threads = B_
        int b = t;
        int e = 0;
        #pragma unroll
        for (int j = 0; j < E_; j++)
            if (y[b * E_ + j] > 0.5f) e = j;
        int warp = t >> 5, lane = t & 31;
        unsigned m = __match_any_sync(0xffffffffu, e);
        int rank = __popc(m & ((1u << lane) - 1u));
        int ldr = __ffs(m) - 1;
        if (t < 32 * E_) ((int*)wcnt)[t] = 0;
        __syncthreads();
        if (lane == ldr) wcnt[warp][e] = __popc(m);
        __syncthreads();
        int off = 0;
        for (int w = 0; w < warp; w++) off += wcnt[w][e];
        g_nodes[e * B_ + off + rank] = b;
        if (t < E_) {
            int tot = 0;
            #pragma unroll
            for (int w = 0; w < 32; w++) tot += wcnt[w][t];
            g_cnt[t] = tot;
        }
    } else if (bid < 71) {        // 69 U3-sym blocks
        int b2 = bid - 2;
        int w = b2 / P3_, k = b2 % P3_;
        for (int i = t; i < NM_; i += 1024) s[i] = 0.f;
        __syncthreads();
        for (int idx = t; idx < 4096; idx += 1024) {
            int xx = idx >> 8, v = (idx >> 4) & 15, i = idx & 15;
            float val = U3[((((w * L_ + xx) * L_ + v) * L_ + i) * P3_) + k];
            int hi = max(xx, max(v, i));
            int lo = min(xx, min(v, i));
            int mid = xx + v + i - hi - lo;
            int mm = Tet(hi) + mid * (mid + 1) / 2 + lo;
            atomicAdd(&s[mm], val);
        }
        __syncthreads();
        for (int mm = t; mm < NM_; mm += 1024)
            g_U3sym[(w * NM_ + mm) * P3_ + k] = s[mm];
    } else if (bid < 86) {        // 15 U2-sym blocks
        int b2 = bid - 71;
        int w = b2 / P2_, k = b2 % P2_;
        if (t < NP_) s[t] = 0.f;
        __syncthreads();
        if (t < 256) {
            int xx = t >> 4, v = t & 15;
            float val = U2[((w * L_ + xx) * L_ + v) * P2_ + k];
            int hi = max(xx, v), lo = min(xx, v);
            int p = hi * (hi + 1) / 2 + lo;
            atomicAdd(&s[p], val);
        }
        __syncthreads();
        if (t < NP_)
            g_U2sym[(w * NP_ + t) * P2_ + k] = s[t];
    }
}

// ---------------- launch 2: coefficient build ----------------------------
// grid 3720 x 256: bid < 840 -> triple-region GEMM tile; else pair/x tail
__global__ __launch_bounds__(256) void k_coeff(
    const float* __restrict__ wmax, const float* __restrict__ U1,
    const float* __restrict__ w2, const float* __restrict__ w1) {
    __shared__ float us[64][24];
    __shared__ float ws[P3_][64];
    __shared__ float outs[64][65];
    int t = threadIdx.x;
    int bid = blockIdx.x;

    if (bid < 840) {
        int row0 = (bid % 42) * 64;
        int ec0 = (bid / 42) * 64;
        int e = ec0 >> 7, c0 = ec0 & 127;

        for (int idx = t; idx < 64 * P3_; idx += 256) {
            int rr = idx / P3_, k = idx % P3_;
            int row = row0 + rr;
            float v = 0.f;
            if (row < EQ_ * NJ3_) {
                int w = row / NJ3_, jj = row - w * NJ3_;
                int m = g_ds_feat[jj];
                if (m != 0xFFFF) v = g_U3sym[(w * NM_ + m) * P3_ + k];
            }
            us[rr][k] = v;
        }
        for (int idx = t; idx < P3_ * 64; idx += 256) {
            int k = idx >> 6, cc = idx & 63;
            ws[k][cc] = wmax[(e * P3_ + k) * C_ + c0 + cc];
        }
        __syncthreads();

        int cc = t & 63, rg = t >> 6;
        float wreg[P3_];
        #pragma unroll
        for (int k = 0; k < P3_; k++) wreg[k] = ws[k][cc];
        #pragma unroll
        for (int rs = 0; rs < 16; rs++) {
            int rr = rg * 16 + rs;
            float acc = 0.f;
            #pragma unroll
            for (int k = 0; k < P3_; k++) acc += us[rr][k] * wreg[k];
            outs[cc][rr] = acc;
        }
        __syncthreads();

        for (int idx = t; idx < 64 * 64; idx += 256) {
            int c2 = idx >> 6, rr = idx & 63;
            int row = row0 + rr;
            if (row < EQ_ * NJ3_) {
                int w = row / NJ3_, jj = row - w * NJ3_;
                g_coeff[(size_t)(ec0 + c2) * CW_ + w * NF_ + jj] = outs[c2][rr];
            }
        }
    } else {
        int i = (bid - 840) * 256 + t;     // exactly 2880*256 = 737280 outputs
        int j2 = i % NJ2_;
        int w  = (i / NJ2_) % EQ_;
        int ec = i / (NJ2_ * EQ_);
        int e = ec >> 7, c = ec & 127;
        float sv = 0.f;
        if (j2 < NP_) {
            #pragma unroll
            for (int k = 0; k < P2_; k++)
                sv += g_U2sym[(w * NP_ + j2) * P2_ + k] * __ldg(&w2[(e * P2_ + k) * C_ + c]);
        } else if (j2 < NP_ + L_) {
            sv = __ldg(&U1[w * L_ + (j2 - NP_)]) * __ldg(&w1[e * C_ + c]);
        }
        g_coeff[(size_t)ec * CW_ + w * NF_ + NJ3_ + j2] = sv;
    }
}

// ---------------- launch 3: main — block per (c,e) -----------------------
// 4 warp-pairs per block; each pair processes 2 nodes per iteration.
// zp buffers: pair pw owns zp[2*pw] (node A) and zp[2*pw+1] (node B, +704B).
// Buffer layout: [0,136) zp values; [168] dummy store sink.
// x lives in registers: lanes 0-15 hold x[i], lanes 16-31 hold 1.0f.
__global__ __launch_bounds__(256, 2) void k_main(
    const float* __restrict__ x, float* __restrict__ out) {
    __shared__ __align__(16) float zp[8][ZSTR_];
    __shared__ float s_red[4][6];

    int t = threadIdx.x;
    int warp = t >> 5, lane = t & 31;
    int pw = warp >> 1;
    int half = warp & 1;
    int c = blockIdx.x, e = blockIdx.y;

    const float* cfb = g_coeff + (size_t)(e * C_ + c) * CW_;
    unsigned zbA = (unsigned)__cvta_generic_to_shared(&zp[pw * 2][0]);

    // packed dual-step coefficients + A-buffer addresses + x source lanes
    ull cd0[7], cd1[7], cd2[7];
    unsigned zsa[7]; int didx[7];
    #pragma unroll
    for (int r = 0; r < 7; r++) {
        int ds = (half * 7 + r) * 32 + lane;
        int j = ds * 2;
        cd0[r] = *(const ull*)(cfb + 0 * NF_ + j);
        cd1[r] = *(const ull*)(cfb + 1 * NF_ + j);
        cd2[r] = *(const ull*)(cfb + 2 * NF_ + j);
        unsigned cc = g_dcode[ds];
        zsa[r] = zbA + (cc & 255u) * 4u;
        didx[r] = cc >> 8;
    }
    // pair-region coefficients + shfl source lanes + store addresses
    float cp0[3], cp1[3], cp2[3];
    int aidx[3], bidx[3]; unsigned sta[3];
    #pragma unroll
    for (int r = 0; r < 3; r++) {
        int j2 = (half * 3 + r) * 32 + lane;
        cp0[r] = cfb[0 * NF_ + NJ3_ + j2];
        cp1[r] = cfb[1 * NF_ + NJ3_ + j2];
        cp2[r] = cfb[2 * NF_ + NJ3_ + j2];
        unsigned cc = g_pcode[j2];
        aidx[r] = cc & 15u;
        bidx[r] = (cc & 256u) ? 16 : ((cc >> 4) & 15u);  // pairs: b lane; isx/pad: lane 16 (=1.0f)
        sta[r] = (j2 < NP_) ? (zbA + (unsigned)j2 * 4u) : (zbA + 168u * 4u);
    }

    int nb = g_cnt[e];
    int jnA = pw * 2;

    // prime: node indices + x prefetch for first iteration
    int bA = (jnA < nb) ? g_nodes[e * B_ + jnA] : -1;
    int bB = (jnA + 1 < nb) ? g_nodes[e * B_ + jnA + 1] : -1;
    float xnA = 1.0f, xnB = 1.0f;
    if (lane < L_) {
        xnA = (bA >= 0) ? __ldg(&x[((size_t)bA * C_ + c) * L_ + lane]) : 0.f;
        xnB = (bB >= 0) ? __ldg(&x[((size_t)bB * C_ + c) * L_ + lane]) : 0.f;
    }

    #define PBAR() asm volatile("bar.sync %0, 64;" :: "r"(pw + 1) : "memory")

    for (; jnA < nb; jnA += 8) {
        float xvA = xnA, xvB = xnB;
        int bcA = bA, bcB = bB;
        int jn2 = jnA + 8;
        bA = (jn2 < nb) ? g_nodes[e * B_ + jn2] : -1;
        bB = (jn2 + 1 < nb) ? g_nodes[e * B_ + jn2 + 1] : -1;

        // pair/x region for both nodes: value -> dot contribution + zp store
        float s0A = 0.f, s1A = 0.f, s2A = 0.f;
        float s0B = 0.f, s1B = 0.f, s2B = 0.f;
        #pragma unroll
        for (int r = 0; r < 3; r++) {
            float vaA = __shfl_sync(0xffffffffu, xvA, aidx[r]);
            float vbA = __shfl_sync(0xffffffffu, xvA, bidx[r]);
            float vaB = __shfl_sync(0xffffffffu, xvB, aidx[r]);
            float vbB = __shfl_sync(0xffffffffu, xvB, bidx[r]);
            float valA = vaA * vbA;
            float valB = vaB * vbB;
            sts_f(sta[r], valA);
            sts_f_B(sta[r], valB);
            s0A = fmaf(cp0[r], valA, s0A);
            s1A = fmaf(cp1[r], valA, s1A);
            s2A = fmaf(cp2[r], valA, s2A);
            s0B = fmaf(cp0[r], valB, s0B);
            s1B = fmaf(cp1[r], valB, s1B);
            s2B = fmaf(cp2[r], valB, s2B);
        }
        // next-iteration x prefetch (hidden behind dual phase)
        xnA = 1.0f; xnB = 1.0f;
        if (lane < L_) {
            xnA = (bA >= 0) ? __ldg(&x[((size_t)bA * C_ + c) * L_ + lane]) : 0.f;
            xnB = (bB >= 0) ? __ldg(&x[((size_t)bB * C_ + c) * L_ + lane]) : 0.f;
        }

        PBAR();   // zp (both buffers) visible across the warp pair

        // fused triple dot: 7 dual steps x 2 nodes, packed f32x2
        ull a0A = 0ull, a1A = 0ull, a2A = 0ull;
        ull a0B = 0ull, a1B = 0ull, a2B = 0ull;
        #pragma unroll
        for (int r = 0; r < 7; r++) {
            ull zA = lds_b64(zsa[r]);
            ull zB = lds_b64_B(zsa[r]);
            float xdA = __shfl_sync(0xffffffffu, xvA, didx[r]);
            float xdB = __shfl_sync(0xffffffffu, xvB, didx[r]);
            ull tpA = mul2(zA, pack2(xdA, xdA));
            ull tpB = mul2(zB, pack2(xdB, xdB));
            a0A = fma2(cd0[r], tpA, a0A);
            a1A = fma2(cd1[r], tpA, a1A);
            a2A = fma2(cd2[r], tpA, a2A);
            a0B = fma2(cd0[r], tpB, a0B);
            a1B = fma2(cd1[r], tpB, a1B);
            a2B = fma2(cd2[r], tpB, a2B);
        }
        float lo, hi;
        unpack2(lo, hi, a0A); float r0A = s0A + lo + hi;
        unpack2(lo, hi, a1A); float r1A = s1A + lo + hi;
        unpack2(lo, hi, a2A); float r2A = s2A + lo + hi;
        unpack2(lo, hi, a0B); float r0B = s0B + lo + hi;
        unpack2(lo, hi, a1B); float r1B = s1B + lo + hi;
        unpack2(lo, hi, a2B); float r2B = s2B + lo + hi;

        // butterfly warp reductions (redux.f32 not available on sm_103)
        #pragma unroll
        for (int msk = 16; msk >= 1; msk >>= 1) {
            r0A += __shfl_xor_sync(0xffffffffu, r0A, msk);
            r1A += __shfl_xor_sync(0xffffffffu, r1A, msk);
            r2A += __shfl_xor_sync(0xffffffffu, r2A, msk);
            r0B += __shfl_xor_sync(0xffffffffu, r0B, msk);
            r1B += __shfl_xor_sync(0xffffffffu, r1B, msk);
            r2B += __shfl_xor_sync(0xffffffffu, r2B, msk);
        }

        if (lane == 0) {
            float* sr = s_red[pw];
            if (half == 1) { sr[0] = r0A; sr[1] = r1A; sr[2] = r2A; }
            else           { sr[3] = r0B; sr[4] = r1B; sr[5] = r2B; }
        }
        PBAR();   // exchange halves; also protects zp/s_red overwrite next iter
        if (lane == 0) {
            const float* sr = s_red[pw];
            if (half == 0) {
                if (bcA >= 0) {
                    float* o = out + ((size_t)bcA * C_ + c) * EQ_;
                    o[0] = r0A + sr[0]; o[1] = r1A + sr[1]; o[2] = r2A + sr[2];
                }
            } else {
                if (bcB >= 0) {
                    float* o = out + ((size_t)bcB * C_ + c) * EQ_;
                    o[0] = r0B + sr[3]; o[1] = r1B + sr[4]; o[2] = r2B + sr[5];
                }
            }
        }
    }
    #undef PBAR
}

extern "C" void kernel_launch(void* const* d_in, const int* in_sizes, int n_in,
                              void* d_out, int out_size) {
    const float* x    = (const float*)d_in[0];
    const float* y    = (const float*)d_in[1];
    const float* U3   = (const float*)d_in[2];
    const float* U2   = (const float*)d_in[3];
    const float* U1   = (const float*)d_in[4];
    const float* wmax = (const float*)d_in[5];
    const float* w2   = (const float*)d_in[6];
    const float* w1   = (const float*)d_in[7];
    float* out = (float*)d_out;

    k_prep<<<86, 1024>>>(y, U3, U2);
    k_coeff<<<3720, 256>>>(wmax, U1, w2, w1);
    k_main<<<dim3(C_, E_), 256>>>(x, out);
}